// round 1
// baseline (speedup 1.0000x reference)
#include <cuda_runtime.h>

// Problem dims (fixed by the dataset): N=20000 nodes, E=320000 edges, B=16,
// node_dim=256, cond_dim=512, out_dim=256.
#define NMAX 20000
#define EMAX 320000
#define BMAX 16

// Scratch (allocation-free rule: __device__ globals)
__device__ float g_x[(size_t)NMAX * 256];      // post-GEMM / post-LN node features
__device__ float g_gamma[BMAX * 256];
__device__ float g_beta[BMAX * 256];
__device__ int   g_cnt[NMAX];
__device__ int   g_off[NMAX + 1];
__device__ int   g_cur[NMAX];
__device__ int   g_perm[EMAX];

// ---------------------------------------------------------------------------
// 1. FiLM params: gb = cond @ Wc + bc ; gamma = gb[:, :256]+1 ; beta = gb[:,256:]
// ---------------------------------------------------------------------------
__global__ void film_kernel(const float* __restrict__ cond,
                            const float* __restrict__ Wc,
                            const float* __restrict__ bc, int B) {
    int tid = blockIdx.x * blockDim.x + threadIdx.x;
    if (tid >= B * 512) return;
    int b = tid >> 9;
    int o = tid & 511;
    const float* c = cond + b * 512;
    float acc = bc[o];
#pragma unroll 4
    for (int k = 0; k < 512; k++) acc = fmaf(c[k], Wc[k * 512 + o], acc);
    if (o < 256) g_gamma[b * 256 + o] = acc + 1.0f;
    else         g_beta[b * 256 + (o - 256)] = acc;
}

// ---------------------------------------------------------------------------
// 2. Node GEMM: x = node_feats[N,256] @ Wl[256,256]  (fp32, tiled)
//    BM=64, BN=64, BK=16, 256 threads, 4x4 microtile
// ---------------------------------------------------------------------------
#define BM 64
#define BN 64
#define BK 16
__global__ void gemm_kernel(const float* __restrict__ A,
                            const float* __restrict__ W, int N) {
    __shared__ float As[BK][68];   // padded (68*4B = 272B, 16B aligned rows)
    __shared__ float Bs[BK][BN];
    int tid = threadIdx.x;
    int m0 = blockIdx.x * BM;
    int n0 = blockIdx.y * BN;
    int tx = tid & 15;
    int ty = tid >> 4;
    float acc[4][4] = {};

    for (int k0 = 0; k0 < 256; k0 += BK) {
#pragma unroll
        for (int i = 0; i < 4; i++) {          // A tile: 64 rows x 16 k (transposed store)
            int idx = tid + i * 256;
            int m = idx >> 4, k = idx & 15;
            int row = m0 + m;
            As[k][m] = (row < N) ? A[(size_t)row * 256 + k0 + k] : 0.0f;
        }
#pragma unroll
        for (int i = 0; i < 4; i++) {          // W tile: 16 k x 64 n
            int idx = tid + i * 256;
            int k = idx >> 6, n = idx & 63;
            Bs[k][n] = W[(size_t)(k0 + k) * 256 + n0 + n];
        }
        __syncthreads();
#pragma unroll
        for (int k = 0; k < BK; k++) {
            float a[4], bb[4];
#pragma unroll
            for (int i = 0; i < 4; i++) a[i] = As[k][ty * 4 + i];
#pragma unroll
            for (int j = 0; j < 4; j++) bb[j] = Bs[k][tx * 4 + j];
#pragma unroll
            for (int i = 0; i < 4; i++)
#pragma unroll
                for (int j = 0; j < 4; j++) acc[i][j] = fmaf(a[i], bb[j], acc[i][j]);
        }
        __syncthreads();
    }
#pragma unroll
    for (int i = 0; i < 4; i++) {
        int row = m0 + ty * 4 + i;
        if (row < N) {
#pragma unroll
            for (int j = 0; j < 4; j++)
                g_x[(size_t)row * 256 + n0 + tx * 4 + j] = acc[i][j];
        }
    }
}

// ---------------------------------------------------------------------------
// 3. LayerNorm (non-affine) + FiLM + ReLU, in place on g_x. One warp per row.
// ---------------------------------------------------------------------------
__global__ void ln_film_kernel(const int* __restrict__ batch_ids, int N) {
    int gw = (blockIdx.x * blockDim.x + threadIdx.x) >> 5;
    int lane = threadIdx.x & 31;
    if (gw >= N) return;
    float4* xr = (float4*)(g_x + (size_t)gw * 256);
    float4 v0 = xr[lane];
    float4 v1 = xr[lane + 32];

    float s = v0.x + v0.y + v0.z + v0.w + v1.x + v1.y + v1.z + v1.w;
#pragma unroll
    for (int o = 16; o; o >>= 1) s += __shfl_xor_sync(0xffffffffu, s, o);
    float mu = s * (1.0f / 256.0f);

    float d, q = 0.0f;
    d = v0.x - mu; q += d * d;  d = v0.y - mu; q += d * d;
    d = v0.z - mu; q += d * d;  d = v0.w - mu; q += d * d;
    d = v1.x - mu; q += d * d;  d = v1.y - mu; q += d * d;
    d = v1.z - mu; q += d * d;  d = v1.w - mu; q += d * d;
#pragma unroll
    for (int o = 16; o; o >>= 1) q += __shfl_xor_sync(0xffffffffu, q, o);
    float rs = rsqrtf(q * (1.0f / 256.0f) + 1e-5f);

    int b = batch_ids[gw];
    const float4* g4 = (const float4*)(g_gamma + b * 256);
    const float4* b4 = (const float4*)(g_beta + b * 256);
    float4 g0 = g4[lane], g1 = g4[lane + 32];
    float4 e0 = b4[lane], e1 = b4[lane + 32];

    v0.x = fmaxf(fmaf((v0.x - mu) * rs, g0.x, e0.x), 0.0f);
    v0.y = fmaxf(fmaf((v0.y - mu) * rs, g0.y, e0.y), 0.0f);
    v0.z = fmaxf(fmaf((v0.z - mu) * rs, g0.z, e0.z), 0.0f);
    v0.w = fmaxf(fmaf((v0.w - mu) * rs, g0.w, e0.w), 0.0f);
    v1.x = fmaxf(fmaf((v1.x - mu) * rs, g1.x, e1.x), 0.0f);
    v1.y = fmaxf(fmaf((v1.y - mu) * rs, g1.y, e1.y), 0.0f);
    v1.z = fmaxf(fmaf((v1.z - mu) * rs, g1.z, e1.z), 0.0f);
    v1.w = fmaxf(fmaf((v1.w - mu) * rs, g1.w, e1.w), 0.0f);

    xr[lane] = v0;
    xr[lane + 32] = v1;
}

// ---------------------------------------------------------------------------
// 4-7. CSR build: zero, histogram of node_i, exclusive scan, fill permutation
// ---------------------------------------------------------------------------
__global__ void zero_kernel(int N) {
    int i = blockIdx.x * blockDim.x + threadIdx.x;
    if (i < N) { g_cnt[i] = 0; g_cur[i] = 0; }
}

__global__ void hist_kernel(const int* __restrict__ ni, int E) {
    int e = blockIdx.x * blockDim.x + threadIdx.x;
    if (e < E) atomicAdd(&g_cnt[ni[e]], 1);
}

__global__ void scan_kernel(int N) {
    __shared__ int sums[1024];
    int t = threadIdx.x;
    int CH = (N + 1023) >> 10;
    int base = t * CH;
    int local = 0;
    for (int i = 0; i < CH; i++) {
        int idx = base + i;
        if (idx < N) local += g_cnt[idx];
    }
    sums[t] = local;
    __syncthreads();
    for (int dd = 1; dd < 1024; dd <<= 1) {
        int v = 0;
        if (t >= dd) v = sums[t - dd];
        __syncthreads();
        if (t >= dd) sums[t] += v;
        __syncthreads();
    }
    int run = sums[t] - local;   // exclusive prefix
    for (int i = 0; i < CH; i++) {
        int idx = base + i;
        if (idx < N) { g_off[idx] = run; run += g_cnt[idx]; }
    }
    if (t == 1023) g_off[N] = sums[1023];
}

__global__ void fill_kernel(const int* __restrict__ ni, int E) {
    int e = blockIdx.x * blockDim.x + threadIdx.x;
    if (e < E) {
        int dst = ni[e];
        int p = atomicAdd(&g_cur[dst], 1);
        g_perm[g_off[dst] + p] = e;
    }
}

// ---------------------------------------------------------------------------
// 8. Pull aggregation: one warp per destination node; gather x[node_j]*w, ReLU
// ---------------------------------------------------------------------------
__global__ void agg_kernel(const int* __restrict__ nj,
                           const float* __restrict__ ew,
                           const float* __restrict__ ep,
                           float* __restrict__ out, int N) {
    int gw = (blockIdx.x * blockDim.x + threadIdx.x) >> 5;
    int lane = threadIdx.x & 31;
    if (gw >= N) return;
    int s = g_off[gw];
    int e = g_off[gw + 1];
    float4 a0 = {0.f, 0.f, 0.f, 0.f};
    float4 a1 = {0.f, 0.f, 0.f, 0.f};
    for (int i = s; i < e; i++) {
        int eid = g_perm[i];
        int j = nj[eid];
        float w = ew[eid] * ep[eid];
        const float4* xr = (const float4*)(g_x + (size_t)j * 256);
        float4 v0 = xr[lane];
        float4 v1 = xr[lane + 32];
        a0.x = fmaf(v0.x, w, a0.x); a0.y = fmaf(v0.y, w, a0.y);
        a0.z = fmaf(v0.z, w, a0.z); a0.w = fmaf(v0.w, w, a0.w);
        a1.x = fmaf(v1.x, w, a1.x); a1.y = fmaf(v1.y, w, a1.y);
        a1.z = fmaf(v1.z, w, a1.z); a1.w = fmaf(v1.w, w, a1.w);
    }
    a0.x = fmaxf(a0.x, 0.f); a0.y = fmaxf(a0.y, 0.f);
    a0.z = fmaxf(a0.z, 0.f); a0.w = fmaxf(a0.w, 0.f);
    a1.x = fmaxf(a1.x, 0.f); a1.y = fmaxf(a1.y, 0.f);
    a1.z = fmaxf(a1.z, 0.f); a1.w = fmaxf(a1.w, 0.f);
    float4* o4 = (float4*)(out + (size_t)gw * 256);
    o4[lane] = a0;
    o4[lane + 32] = a1;
}

// ---------------------------------------------------------------------------
extern "C" void kernel_launch(void* const* d_in, const int* in_sizes, int n_in,
                              void* d_out, int out_size) {
    const float* node_feats = (const float*)d_in[0];
    const float* cond_feats = (const float*)d_in[1];
    const int*   batch_ids  = (const int*)d_in[2];
    const int*   node_j     = (const int*)d_in[3];
    const int*   node_i     = (const int*)d_in[4];
    const float* edge_w     = (const float*)d_in[5];
    const float* edge_p     = (const float*)d_in[6];
    const float* Wc         = (const float*)d_in[7];
    const float* bc         = (const float*)d_in[8];
    const float* Wl         = (const float*)d_in[9];
    float* out = (float*)d_out;

    int N = in_sizes[0] / 256;
    int B = in_sizes[1] / 512;
    int E = in_sizes[3];

    film_kernel<<<(B * 512 + 255) / 256, 256>>>(cond_feats, Wc, bc, B);
    gemm_kernel<<<dim3((N + BM - 1) / BM, 256 / BN), 256>>>(node_feats, Wl, N);
    ln_film_kernel<<<(N * 32 + 255) / 256, 256>>>(batch_ids, N);
    zero_kernel<<<(N + 255) / 256, 256>>>(N);
    hist_kernel<<<(E + 255) / 256, 256>>>(node_i, E);
    scan_kernel<<<1, 1024>>>(N);
    fill_kernel<<<(E + 255) / 256, 256>>>(node_i, E);
    agg_kernel<<<(N * 32 + 255) / 256, 256>>>(node_j, edge_w, edge_p, out, N);
}

// round 2
// speedup vs baseline: 1.1490x; 1.1490x over previous
#include <cuda_runtime.h>

// Problem dims (fixed by dataset): N=20000, E=320000, B=16,
// node_dim=256, cond_dim=512, out_dim=256.
#define NMAX 20000
#define EMAX 320000
#define BMAX 16

// Scratch (allocation-free rule: __device__ globals)
__device__ __align__(16) float g_x[(size_t)NMAX * 256];
__device__ __align__(16) float g_gamma[BMAX * 256];
__device__ __align__(16) float g_beta[BMAX * 256];
__device__ int   g_cnt[NMAX];
__device__ int   g_off[NMAX + 1];
__device__ int   g_cur[NMAX];
__device__ int   g_src[EMAX];    // node_j permuted into CSR order
__device__ float g_wgt[EMAX];    // ew*ep permuted into CSR order

// Packed f32x2 FMA: d.lo = fma(a.lo,b.lo,d.lo), d.hi = fma(a.hi,b.hi,d.hi)
#define FMA_F32X2(d, a, b) \
    asm("fma.rn.f32x2 %0, %1, %2, %0;" : "+l"(d) : "l"(a), "l"(b))
#define PACK_DUP(d, f) \
    asm("mov.b64 %0, {%1, %1};" : "=l"(d) : "r"(__float_as_uint(f)))
#define UNPACK2F(lo, hi, v) do { unsigned _ulo, _uhi; \
    asm("mov.b64 {%0, %1}, %2;" : "=r"(_ulo), "=r"(_uhi) : "l"(v)); \
    lo = __uint_as_float(_ulo); hi = __uint_as_float(_uhi); } while (0)

// ---------------------------------------------------------------------------
// 1. FiLM params (gb = cond @ Wc + bc; gamma = gb[:,:256]+1, beta = gb[:,256:])
//    + zero the CSR counters (merged to save a launch).
// ---------------------------------------------------------------------------
__global__ void film_zero_kernel(const float* __restrict__ cond,
                                 const float* __restrict__ Wc,
                                 const float* __restrict__ bc, int B, int N) {
    int tid = blockIdx.x * blockDim.x + threadIdx.x;
    for (int i = tid; i < N; i += gridDim.x * blockDim.x) {
        g_cnt[i] = 0; g_cur[i] = 0;
    }
    if (tid >= B * 512) return;
    int b = tid >> 9;
    int o = tid & 511;
    const float* c = cond + b * 512;
    float acc = bc[o];
#pragma unroll 4
    for (int k = 0; k < 512; k++) acc = fmaf(c[k], Wc[k * 512 + o], acc);
    if (o < 256) g_gamma[b * 256 + o] = acc + 1.0f;
    else         g_beta[b * 256 + (o - 256)] = acc;
}

// ---------------------------------------------------------------------------
// 2. Fused GEMM + LayerNorm + FiLM + ReLU.
//    x = node_feats[N,256] @ Wl[256,256], then per-row LN, FiLM, ReLU -> g_x.
//    Tile: BM=64 x BN=256 (full row), BK=16. 256 threads (8 warps).
//    Warp ty owns rows m0+ty*8 .. +7 across all 256 cols.
//    Thread (ty,tx) computes 8 rows x cols {tx*4..+3, 128+tx*4..+3}
//    using packed f32x2 FMAs (2x fp32 throughput).
// ---------------------------------------------------------------------------
#define GBM 64
#define GBK 16
__global__ void __launch_bounds__(256, 2)
gemm_ln_kernel(const float* __restrict__ A,
               const float* __restrict__ W,
               const int* __restrict__ batch_ids, int N) {
    __shared__ float As[GBM][20];    // [m][k], pad 20 (16B-aligned rows)
    __shared__ float Bs[GBK][260];   // [k][n], pad 260 (16B-aligned rows)

    int tid = threadIdx.x;
    int tx = tid & 31, ty = tid >> 5;
    int m0 = blockIdx.x * GBM;

    // A-tile load mapping: thread -> (row am, k-chunk ak)
    int am = tid >> 2;
    int ak = (tid & 3) * 4;
    int arow = m0 + am;
    const float4* Arow = (arow < N) ? (const float4*)(A + (size_t)arow * 256) : 0;

    // B-tile load mapping: 4 float4 per thread
    int bkb = tid >> 6;          // 0..3 base k (strided by 4 over i)
    int bn = (tid & 63) * 4;     // n offset

    // accumulators: 8 rows x 4 f32x2 pairs (cols tx*4,+1 | +2,+3 | 128+tx*4.. )
    unsigned long long acc[8][4];
#pragma unroll
    for (int i = 0; i < 8; i++)
#pragma unroll
        for (int j = 0; j < 4; j++) acc[i][j] = 0ULL;

    // prefetch tile 0
    float4 aR = make_float4(0.f, 0.f, 0.f, 0.f);
    if (Arow) aR = Arow[(tid & 3)];
    float4 bR[4];
#pragma unroll
    for (int i = 0; i < 4; i++)
        bR[i] = *(const float4*)(W + (size_t)(bkb + 4 * i) * 256 + bn);

    for (int kt = 0; kt < 16; kt++) {
        *(float4*)&As[am][ak] = aR;
#pragma unroll
        for (int i = 0; i < 4; i++)
            *(float4*)&Bs[bkb + 4 * i][bn] = bR[i];
        __syncthreads();

        if (kt < 15) {
            int k0n = (kt + 1) * 16;
            aR = make_float4(0.f, 0.f, 0.f, 0.f);
            if (Arow) aR = Arow[k0n / 4 + (tid & 3)];
#pragma unroll
            for (int i = 0; i < 4; i++)
                bR[i] = *(const float4*)(W + (size_t)(k0n + bkb + 4 * i) * 256 + bn);
        }

#pragma unroll
        for (int k = 0; k < GBK; k++) {
            ulonglong2 b0 = *(const ulonglong2*)&Bs[k][tx * 4];
            ulonglong2 b1 = *(const ulonglong2*)&Bs[k][128 + tx * 4];
#pragma unroll
            for (int i = 0; i < 8; i++) {
                float av = As[ty * 8 + i][k];      // warp broadcast
                unsigned long long aa;
                PACK_DUP(aa, av);
                FMA_F32X2(acc[i][0], aa, b0.x);
                FMA_F32X2(acc[i][1], aa, b0.y);
                FMA_F32X2(acc[i][2], aa, b1.x);
                FMA_F32X2(acc[i][3], aa, b1.y);
            }
        }
        __syncthreads();
    }

    // ---- epilogue: per-row LayerNorm + FiLM + ReLU, write g_x ----
#pragma unroll
    for (int i = 0; i < 8; i++) {
        float v[8];
        UNPACK2F(v[0], v[1], acc[i][0]);
        UNPACK2F(v[2], v[3], acc[i][1]);
        UNPACK2F(v[4], v[5], acc[i][2]);
        UNPACK2F(v[6], v[7], acc[i][3]);

        float ps = 0.f, pq = 0.f;
#pragma unroll
        for (int j = 0; j < 8; j++) { ps += v[j]; pq = fmaf(v[j], v[j], pq); }
#pragma unroll
        for (int o = 16; o; o >>= 1) {
            ps += __shfl_xor_sync(0xffffffffu, ps, o);
            pq += __shfl_xor_sync(0xffffffffu, pq, o);
        }
        float mu = ps * (1.0f / 256.0f);
        float var = fmaxf(pq * (1.0f / 256.0f) - mu * mu, 0.0f);
        float rs = rsqrtf(var + 1e-5f);

        int row = m0 + ty * 8 + i;
        if (row < N) {
            int b = batch_ids[row];
            const float4* g4 = (const float4*)(g_gamma + b * 256);
            const float4* e4 = (const float4*)(g_beta + b * 256);
            float4 gA = g4[tx], gB = g4[tx + 32];
            float4 eA = e4[tx], eB = e4[tx + 32];

            float4 o0, o1;
            o0.x = fmaxf(fmaf((v[0] - mu) * rs, gA.x, eA.x), 0.f);
            o0.y = fmaxf(fmaf((v[1] - mu) * rs, gA.y, eA.y), 0.f);
            o0.z = fmaxf(fmaf((v[2] - mu) * rs, gA.z, eA.z), 0.f);
            o0.w = fmaxf(fmaf((v[3] - mu) * rs, gA.w, eA.w), 0.f);
            o1.x = fmaxf(fmaf((v[4] - mu) * rs, gB.x, eB.x), 0.f);
            o1.y = fmaxf(fmaf((v[5] - mu) * rs, gB.y, eB.y), 0.f);
            o1.z = fmaxf(fmaf((v[6] - mu) * rs, gB.z, eB.z), 0.f);
            o1.w = fmaxf(fmaf((v[7] - mu) * rs, gB.w, eB.w), 0.f);

            float4* xr = (float4*)(g_x + (size_t)row * 256);
            xr[tx] = o0;
            xr[tx + 32] = o1;
        }
    }
}

// ---------------------------------------------------------------------------
// 3-5. CSR build: histogram of node_i, exclusive scan, fill (permute payloads)
// ---------------------------------------------------------------------------
__global__ void hist_kernel(const int* __restrict__ ni, int E) {
    int e = blockIdx.x * blockDim.x + threadIdx.x;
    if (e < E) atomicAdd(&g_cnt[ni[e]], 1);
}

__global__ void scan_kernel(int N) {
    __shared__ int sums[1024];
    int t = threadIdx.x;
    int CH = (N + 1023) >> 10;
    int base = t * CH;
    int local = 0;
    for (int i = 0; i < CH; i++) {
        int idx = base + i;
        if (idx < N) local += g_cnt[idx];
    }
    sums[t] = local;
    __syncthreads();
    for (int dd = 1; dd < 1024; dd <<= 1) {
        int v = 0;
        if (t >= dd) v = sums[t - dd];
        __syncthreads();
        if (t >= dd) sums[t] += v;
        __syncthreads();
    }
    int run = sums[t] - local;   // exclusive prefix
    for (int i = 0; i < CH; i++) {
        int idx = base + i;
        if (idx < N) { g_off[idx] = run; run += g_cnt[idx]; }
    }
    if (t == 1023) g_off[N] = sums[1023];
}

__global__ void fill_kernel(const int* __restrict__ ni,
                            const int* __restrict__ nj,
                            const float* __restrict__ ew,
                            const float* __restrict__ ep, int E) {
    int e = blockIdx.x * blockDim.x + threadIdx.x;
    if (e < E) {
        int dst = ni[e];
        int p = atomicAdd(&g_cur[dst], 1);
        int pos = g_off[dst] + p;
        g_src[pos] = nj[e];
        g_wgt[pos] = ew[e] * ep[e];
    }
}

// ---------------------------------------------------------------------------
// 6. Pull aggregation: warp per destination node; sequential CSR payloads.
// ---------------------------------------------------------------------------
__global__ void agg_kernel(float* __restrict__ out, int N) {
    int gw = (blockIdx.x * blockDim.x + threadIdx.x) >> 5;
    int lane = threadIdx.x & 31;
    if (gw >= N) return;
    int s = g_off[gw];
    int e = g_off[gw + 1];
    float4 a0 = {0.f, 0.f, 0.f, 0.f};
    float4 a1 = {0.f, 0.f, 0.f, 0.f};
    for (int i = s; i < e; i++) {
        int j = g_src[i];
        float w = g_wgt[i];
        const float4* xr = (const float4*)(g_x + (size_t)j * 256);
        float4 v0 = xr[lane];
        float4 v1 = xr[lane + 32];
        a0.x = fmaf(v0.x, w, a0.x); a0.y = fmaf(v0.y, w, a0.y);
        a0.z = fmaf(v0.z, w, a0.z); a0.w = fmaf(v0.w, w, a0.w);
        a1.x = fmaf(v1.x, w, a1.x); a1.y = fmaf(v1.y, w, a1.y);
        a1.z = fmaf(v1.z, w, a1.z); a1.w = fmaf(v1.w, w, a1.w);
    }
    a0.x = fmaxf(a0.x, 0.f); a0.y = fmaxf(a0.y, 0.f);
    a0.z = fmaxf(a0.z, 0.f); a0.w = fmaxf(a0.w, 0.f);
    a1.x = fmaxf(a1.x, 0.f); a1.y = fmaxf(a1.y, 0.f);
    a1.z = fmaxf(a1.z, 0.f); a1.w = fmaxf(a1.w, 0.f);
    float4* o4 = (float4*)(out + (size_t)gw * 256);
    o4[lane] = a0;
    o4[lane + 32] = a1;
}

// ---------------------------------------------------------------------------
extern "C" void kernel_launch(void* const* d_in, const int* in_sizes, int n_in,
                              void* d_out, int out_size) {
    const float* node_feats = (const float*)d_in[0];
    const float* cond_feats = (const float*)d_in[1];
    const int*   batch_ids  = (const int*)d_in[2];
    const int*   node_j     = (const int*)d_in[3];
    const int*   node_i     = (const int*)d_in[4];
    const float* edge_w     = (const float*)d_in[5];
    const float* edge_p     = (const float*)d_in[6];
    const float* Wc         = (const float*)d_in[7];
    const float* bc         = (const float*)d_in[8];
    const float* Wl         = (const float*)d_in[9];
    float* out = (float*)d_out;

    int N = in_sizes[0] / 256;
    int B = in_sizes[1] / 512;
    int E = in_sizes[3];

    film_zero_kernel<<<40, 256>>>(cond_feats, Wc, bc, B, N);
    gemm_ln_kernel<<<(N + GBM - 1) / GBM, 256>>>(node_feats, Wl, batch_ids, N);
    hist_kernel<<<(E + 255) / 256, 256>>>(node_i, E);
    scan_kernel<<<1, 1024>>>(N);
    fill_kernel<<<(E + 255) / 256, 256>>>(node_i, node_j, edge_w, edge_p, E);
    agg_kernel<<<(N * 32 + 255) / 256, 256>>>(out, N);
}

// round 3
// speedup vs baseline: 1.1803x; 1.0272x over previous
#include <cuda_runtime.h>

// Problem dims (fixed by dataset): N=20000, E=320000, B=16,
// node_dim=256, cond_dim=512, out_dim=256.
#define NMAX 20000
#define EMAX 320000
#define BMAX 16

// Scratch (allocation-free rule: __device__ globals)
__device__ __align__(16) float g_x[(size_t)NMAX * 256];
__device__ __align__(16) float g_gamma[BMAX * 256];
__device__ __align__(16) float g_beta[BMAX * 256];
__device__ int   g_cnt[NMAX];
__device__ int   g_off[NMAX + 1];
__device__ int   g_cur[NMAX];
__device__ int   g_blk[128];     // per-block sums for 2-level scan
__device__ int   g_src[EMAX];    // node_j permuted into CSR order
__device__ float g_wgt[EMAX];    // ew*ep permuted into CSR order

// Packed f32x2 FMA: d.lo = fma(a.lo,b.lo,d.lo), d.hi = fma(a.hi,b.hi,d.hi)
#define FMA_F32X2(d, a, b) \
    asm("fma.rn.f32x2 %0, %1, %2, %0;" : "+l"(d) : "l"(a), "l"(b))
#define UNPACK2F(lo, hi, v) do { unsigned _ulo, _uhi; \
    asm("mov.b64 {%0, %1}, %2;" : "=r"(_ulo), "=r"(_uhi) : "l"(v)); \
    lo = __uint_as_float(_ulo); hi = __uint_as_float(_uhi); } while (0)

// ---------------------------------------------------------------------------
// 1. FiLM params (gb = cond @ Wc + bc) + zero CSR counters (merged launch).
// ---------------------------------------------------------------------------
__global__ void film_zero_kernel(const float* __restrict__ cond,
                                 const float* __restrict__ Wc,
                                 const float* __restrict__ bc, int B, int N) {
    int tid = blockIdx.x * blockDim.x + threadIdx.x;
    for (int i = tid; i < N; i += gridDim.x * blockDim.x) {
        g_cnt[i] = 0; g_cur[i] = 0;
    }
    if (tid >= B * 512) return;
    int b = tid >> 9;
    int o = tid & 511;
    const float* c = cond + b * 512;
    float acc = bc[o];
#pragma unroll 4
    for (int k = 0; k < 512; k++) acc = fmaf(c[k], Wc[k * 512 + o], acc);
    if (o < 256) g_gamma[b * 256 + o] = acc + 1.0f;
    else         g_beta[b * 256 + (o - 256)] = acc;
}

// ---------------------------------------------------------------------------
// 2. hist: count edges per destination node.
// ---------------------------------------------------------------------------
__global__ void hist_kernel(const int* __restrict__ ni, int E) {
    int e = blockIdx.x * blockDim.x + threadIdx.x;
    if (e < E) atomicAdd(&g_cnt[ni[e]], 1);
}

// ---------------------------------------------------------------------------
// 3. scan_part: per-block exclusive scan (coalesced), write block sums.
//    256 threads/block, 1 element per thread.
// ---------------------------------------------------------------------------
__global__ void scan_part_kernel(int N) {
    __shared__ int wsum[8];
    int idx = blockIdx.x * 256 + threadIdx.x;
    int lane = threadIdx.x & 31;
    int wid = threadIdx.x >> 5;
    int v = (idx < N) ? g_cnt[idx] : 0;
    // warp inclusive scan
    int s = v;
#pragma unroll
    for (int o = 1; o < 32; o <<= 1) {
        int t = __shfl_up_sync(0xffffffffu, s, o);
        if (lane >= o) s += t;
    }
    if (lane == 31) wsum[wid] = s;
    __syncthreads();
    if (wid == 0) {
        int ws = (lane < 8) ? wsum[lane] : 0;
#pragma unroll
        for (int o = 1; o < 8; o <<= 1) {
            int t = __shfl_up_sync(0xffffffffu, ws, o);
            if (lane >= o) ws += t;
        }
        if (lane < 8) wsum[lane] = ws;
    }
    __syncthreads();
    int excl = s - v + (wid ? wsum[wid - 1] : 0);
    if (idx < N) g_off[idx] = excl;
    if (threadIdx.x == 255) g_blk[blockIdx.x] = excl + v;
}

// ---------------------------------------------------------------------------
// 5. scan_add: add prefix of block sums; g_off[N] = E (known).
// ---------------------------------------------------------------------------
__global__ void scan_add_kernel(int N, int E, int nblk) {
    __shared__ int prefix;
    int bid = blockIdx.x;
    if (threadIdx.x < 32) {
        int acc = 0;
        for (int t = threadIdx.x; t < bid; t += 32) acc += g_blk[t];
#pragma unroll
        for (int o = 16; o; o >>= 1) acc += __shfl_xor_sync(0xffffffffu, acc, o);
        if (threadIdx.x == 0) prefix = acc;
    }
    __syncthreads();
    int idx = bid * 256 + threadIdx.x;
    if (idx < N && bid > 0) g_off[idx] += prefix;
    if (idx == 0) g_off[N] = E;
}

// ---------------------------------------------------------------------------
// 4. Fused GEMM + LayerNorm + FiLM + ReLU (launched 4th for ncu capture).
//    BM=64 x BN=256, BK=16, 256 threads. A tile stored DUPLICATED (float2
//    {a,a}) so the hot loop is LDS.64 broadcast + FFMA2 only.
// ---------------------------------------------------------------------------
#define GBM 64
#define GBK 16
__global__ void __launch_bounds__(256, 2)
gemm_ln_kernel(const float* __restrict__ A,
               const float* __restrict__ W,
               const int* __restrict__ batch_ids, int N) {
    __shared__ float2 As2[GBK][GBM + 1];  // [k][m] duplicated pairs, padded
    __shared__ float  Bs[GBK][260];       // [k][n], padded to 16B-aligned rows

    int tid = threadIdx.x;
    int tx = tid & 31, ty = tid >> 5;
    int m0 = blockIdx.x * GBM;

    // A-tile load mapping: thread -> (row am, k-chunk ak=4 consecutive k)
    int am = tid >> 2;
    int ak = (tid & 3) * 4;
    int arow = m0 + am;
    const float4* Arow = (arow < N) ? (const float4*)(A + (size_t)arow * 256) : 0;

    // B-tile load mapping: 4 float4 per thread
    int bkb = tid >> 6;          // base k, strided by 4
    int bn = (tid & 63) * 4;     // n offset

    unsigned long long acc[8][4];
#pragma unroll
    for (int i = 0; i < 8; i++)
#pragma unroll
        for (int j = 0; j < 4; j++) acc[i][j] = 0ULL;

    // prefetch tile 0
    float4 aR = make_float4(0.f, 0.f, 0.f, 0.f);
    if (Arow) aR = Arow[(tid & 3)];
    float4 bR[4];
#pragma unroll
    for (int i = 0; i < 4; i++)
        bR[i] = *(const float4*)(W + (size_t)(bkb + 4 * i) * 256 + bn);

    for (int kt = 0; kt < 16; kt++) {
        As2[ak + 0][am] = make_float2(aR.x, aR.x);
        As2[ak + 1][am] = make_float2(aR.y, aR.y);
        As2[ak + 2][am] = make_float2(aR.z, aR.z);
        As2[ak + 3][am] = make_float2(aR.w, aR.w);
#pragma unroll
        for (int i = 0; i < 4; i++)
            *(float4*)&Bs[bkb + 4 * i][bn] = bR[i];
        __syncthreads();

        if (kt < 15) {
            int k0n = (kt + 1) * 16;
            aR = make_float4(0.f, 0.f, 0.f, 0.f);
            if (Arow) aR = Arow[k0n / 4 + (tid & 3)];
#pragma unroll
            for (int i = 0; i < 4; i++)
                bR[i] = *(const float4*)(W + (size_t)(k0n + bkb + 4 * i) * 256 + bn);
        }

#pragma unroll
        for (int k = 0; k < GBK; k++) {
            ulonglong2 b0 = *(const ulonglong2*)&Bs[k][tx * 4];
            ulonglong2 b1 = *(const ulonglong2*)&Bs[k][128 + tx * 4];
#pragma unroll
            for (int i = 0; i < 8; i++) {
                unsigned long long aa =
                    *(const unsigned long long*)&As2[k][ty * 8 + i];
                FMA_F32X2(acc[i][0], aa, b0.x);
                FMA_F32X2(acc[i][1], aa, b0.y);
                FMA_F32X2(acc[i][2], aa, b1.x);
                FMA_F32X2(acc[i][3], aa, b1.y);
            }
        }
        __syncthreads();
    }

    // ---- epilogue: per-row LayerNorm + FiLM + ReLU, write g_x ----
#pragma unroll
    for (int i = 0; i < 8; i++) {
        float v[8];
        UNPACK2F(v[0], v[1], acc[i][0]);
        UNPACK2F(v[2], v[3], acc[i][1]);
        UNPACK2F(v[4], v[5], acc[i][2]);
        UNPACK2F(v[6], v[7], acc[i][3]);

        float ps = 0.f, pq = 0.f;
#pragma unroll
        for (int j = 0; j < 8; j++) { ps += v[j]; pq = fmaf(v[j], v[j], pq); }
#pragma unroll
        for (int o = 16; o; o >>= 1) {
            ps += __shfl_xor_sync(0xffffffffu, ps, o);
            pq += __shfl_xor_sync(0xffffffffu, pq, o);
        }
        float mu = ps * (1.0f / 256.0f);
        float var = fmaxf(pq * (1.0f / 256.0f) - mu * mu, 0.0f);
        float rs = rsqrtf(var + 1e-5f);

        int row = m0 + ty * 8 + i;
        if (row < N) {
            int b = batch_ids[row];
            const float4* g4 = (const float4*)(g_gamma + b * 256);
            const float4* e4 = (const float4*)(g_beta + b * 256);
            float4 gA = g4[tx], gB = g4[tx + 32];
            float4 eA = e4[tx], eB = e4[tx + 32];

            float4 o0, o1;
            o0.x = fmaxf(fmaf((v[0] - mu) * rs, gA.x, eA.x), 0.f);
            o0.y = fmaxf(fmaf((v[1] - mu) * rs, gA.y, eA.y), 0.f);
            o0.z = fmaxf(fmaf((v[2] - mu) * rs, gA.z, eA.z), 0.f);
            o0.w = fmaxf(fmaf((v[3] - mu) * rs, gA.w, eA.w), 0.f);
            o1.x = fmaxf(fmaf((v[4] - mu) * rs, gB.x, eB.x), 0.f);
            o1.y = fmaxf(fmaf((v[5] - mu) * rs, gB.y, eB.y), 0.f);
            o1.z = fmaxf(fmaf((v[6] - mu) * rs, gB.z, eB.z), 0.f);
            o1.w = fmaxf(fmaf((v[7] - mu) * rs, gB.w, eB.w), 0.f);

            float4* xr = (float4*)(g_x + (size_t)row * 256);
            xr[tx] = o0;
            xr[tx + 32] = o1;
        }
    }
}

// ---------------------------------------------------------------------------
// 6. fill: permute edge payloads into CSR order.
// ---------------------------------------------------------------------------
__global__ void fill_kernel(const int* __restrict__ ni,
                            const int* __restrict__ nj,
                            const float* __restrict__ ew,
                            const float* __restrict__ ep, int E) {
    int e = blockIdx.x * blockDim.x + threadIdx.x;
    if (e < E) {
        int dst = ni[e];
        int p = atomicAdd(&g_cur[dst], 1);
        int pos = g_off[dst] + p;
        g_src[pos] = nj[e];
        g_wgt[pos] = ew[e] * ep[e];
    }
}

// ---------------------------------------------------------------------------
// 7. Pull aggregation: warp per destination node; sequential CSR payloads.
// ---------------------------------------------------------------------------
__global__ void agg_kernel(float* __restrict__ out, int N) {
    int gw = (blockIdx.x * blockDim.x + threadIdx.x) >> 5;
    int lane = threadIdx.x & 31;
    if (gw >= N) return;
    int s = g_off[gw];
    int e = g_off[gw + 1];
    float4 a0 = {0.f, 0.f, 0.f, 0.f};
    float4 a1 = {0.f, 0.f, 0.f, 0.f};
    for (int i = s; i < e; i++) {
        int j = g_src[i];
        float w = g_wgt[i];
        const float4* xr = (const float4*)(g_x + (size_t)j * 256);
        float4 v0 = xr[lane];
        float4 v1 = xr[lane + 32];
        a0.x = fmaf(v0.x, w, a0.x); a0.y = fmaf(v0.y, w, a0.y);
        a0.z = fmaf(v0.z, w, a0.z); a0.w = fmaf(v0.w, w, a0.w);
        a1.x = fmaf(v1.x, w, a1.x); a1.y = fmaf(v1.y, w, a1.y);
        a1.z = fmaf(v1.z, w, a1.z); a1.w = fmaf(v1.w, w, a1.w);
    }
    a0.x = fmaxf(a0.x, 0.f); a0.y = fmaxf(a0.y, 0.f);
    a0.z = fmaxf(a0.z, 0.f); a0.w = fmaxf(a0.w, 0.f);
    a1.x = fmaxf(a1.x, 0.f); a1.y = fmaxf(a1.y, 0.f);
    a1.z = fmaxf(a1.z, 0.f); a1.w = fmaxf(a1.w, 0.f);
    float4* o4 = (float4*)(out + (size_t)gw * 256);
    o4[lane] = a0;
    o4[lane + 32] = a1;
}

// ---------------------------------------------------------------------------
extern "C" void kernel_launch(void* const* d_in, const int* in_sizes, int n_in,
                              void* d_out, int out_size) {
    const float* node_feats = (const float*)d_in[0];
    const float* cond_feats = (const float*)d_in[1];
    const int*   batch_ids  = (const int*)d_in[2];
    const int*   node_j     = (const int*)d_in[3];
    const int*   node_i     = (const int*)d_in[4];
    const float* edge_w     = (const float*)d_in[5];
    const float* edge_p     = (const float*)d_in[6];
    const float* Wc         = (const float*)d_in[7];
    const float* bc         = (const float*)d_in[8];
    const float* Wl         = (const float*)d_in[9];
    float* out = (float*)d_out;

    int N = in_sizes[0] / 256;
    int B = in_sizes[1] / 512;
    int E = in_sizes[3];
    int nblk = (N + 255) / 256;

    // Order chosen so gemm_ln is the 4th launch (ncu capture alignment).
    film_zero_kernel<<<40, 256>>>(cond_feats, Wc, bc, B, N);
    hist_kernel<<<(E + 255) / 256, 256>>>(node_i, E);
    scan_part_kernel<<<nblk, 256>>>(N);
    gemm_ln_kernel<<<(N + GBM - 1) / GBM, 256>>>(node_feats, Wl, batch_ids, N);
    scan_add_kernel<<<nblk, 256>>>(N, E, nblk);
    fill_kernel<<<(E + 255) / 256, 256>>>(node_i, node_j, edge_w, edge_p, E);
    agg_kernel<<<(N * 32 + 255) / 256, 256>>>(out, N);
}

// round 4
// speedup vs baseline: 1.2886x; 1.0918x over previous
#include <cuda_runtime.h>

// Problem dims (fixed by dataset): N=20000, E=320000, B=16,
// node_dim=256, cond_dim=512, out_dim=256.
#define NMAX 20000
#define EMAX 320000
#define BMAX 16

// Scratch (allocation-free rule: __device__ globals)
__device__ __align__(16) float g_x[(size_t)NMAX * 256];
__device__ __align__(16) float g_gamma[BMAX * 256];
__device__ __align__(16) float g_beta[BMAX * 256];
__device__ int   g_cnt[NMAX];
__device__ int   g_off[NMAX + 1];
__device__ int   g_cur[NMAX];
__device__ int   g_blk[128];     // per-block sums for 2-level scan
__device__ int   g_src[EMAX];    // node_j permuted into CSR order
__device__ float g_wgt[EMAX];    // ew*ep permuted into CSR order

// Packed f32x2 FMA: d.lo = fma(a.lo,b.lo,d.lo), d.hi = fma(a.hi,b.hi,d.hi)
#define FMA_F32X2(d, a, b) \
    asm("fma.rn.f32x2 %0, %1, %2, %0;" : "+l"(d) : "l"(a), "l"(b))
#define PACK_DUP(d, f) \
    asm("mov.b64 %0, {%1, %1};" : "=l"(d) : "r"(__float_as_uint(f)))
#define UNPACK2F(lo, hi, v) do { unsigned _ulo, _uhi; \
    asm("mov.b64 {%0, %1}, %2;" : "=r"(_ulo), "=r"(_uhi) : "l"(v)); \
    lo = __uint_as_float(_ulo); hi = __uint_as_float(_uhi); } while (0)

// ---------------------------------------------------------------------------
// 1. FiLM params (gb = cond @ Wc + bc) + zero CSR counters (merged launch).
// ---------------------------------------------------------------------------
__global__ void film_zero_kernel(const float* __restrict__ cond,
                                 const float* __restrict__ Wc,
                                 const float* __restrict__ bc, int B, int N) {
    int tid = blockIdx.x * blockDim.x + threadIdx.x;
    for (int i = tid; i < N; i += gridDim.x * blockDim.x) {
        g_cnt[i] = 0; g_cur[i] = 0;
    }
    if (tid >= B * 512) return;
    int b = tid >> 9;
    int o = tid & 511;
    const float* c = cond + b * 512;
    float acc = bc[o];
#pragma unroll 4
    for (int k = 0; k < 512; k++) acc = fmaf(c[k], Wc[k * 512 + o], acc);
    if (o < 256) g_gamma[b * 256 + o] = acc + 1.0f;
    else         g_beta[b * 256 + (o - 256)] = acc;
}

// ---------------------------------------------------------------------------
// 2. hist: count edges per destination node.
// ---------------------------------------------------------------------------
__global__ void hist_kernel(const int* __restrict__ ni, int E) {
    int e = blockIdx.x * blockDim.x + threadIdx.x;
    if (e < E) atomicAdd(&g_cnt[ni[e]], 1);
}

// ---------------------------------------------------------------------------
// 3. scan_part: per-block exclusive scan (coalesced), write block sums.
// ---------------------------------------------------------------------------
__global__ void scan_part_kernel(int N) {
    __shared__ int wsum[8];
    int idx = blockIdx.x * 256 + threadIdx.x;
    int lane = threadIdx.x & 31;
    int wid = threadIdx.x >> 5;
    int v = (idx < N) ? g_cnt[idx] : 0;
    int s = v;
#pragma unroll
    for (int o = 1; o < 32; o <<= 1) {
        int t = __shfl_up_sync(0xffffffffu, s, o);
        if (lane >= o) s += t;
    }
    if (lane == 31) wsum[wid] = s;
    __syncthreads();
    if (wid == 0) {
        int ws = (lane < 8) ? wsum[lane] : 0;
#pragma unroll
        for (int o = 1; o < 8; o <<= 1) {
            int t = __shfl_up_sync(0xffffffffu, ws, o);
            if (lane >= o) ws += t;
        }
        if (lane < 8) wsum[lane] = ws;
    }
    __syncthreads();
    int excl = s - v + (wid ? wsum[wid - 1] : 0);
    if (idx < N) g_off[idx] = excl;
    if (threadIdx.x == 255) g_blk[blockIdx.x] = excl + v;
}

// ---------------------------------------------------------------------------
// 5. scan_add: add prefix of block sums; g_off[N] = E (known).
// ---------------------------------------------------------------------------
__global__ void scan_add_kernel(int N, int E, int nblk) {
    __shared__ int prefix;
    int bid = blockIdx.x;
    if (threadIdx.x < 32) {
        int acc = 0;
        for (int t = threadIdx.x; t < bid; t += 32) acc += g_blk[t];
#pragma unroll
        for (int o = 16; o; o >>= 1) acc += __shfl_xor_sync(0xffffffffu, acc, o);
        if (threadIdx.x == 0) prefix = acc;
    }
    __syncthreads();
    int idx = bid * 256 + threadIdx.x;
    if (idx < N && bid > 0) g_off[idx] += prefix;
    if (idx == 0) g_off[N] = E;
}

// ---------------------------------------------------------------------------
// 4. Fused GEMM + LayerNorm + FiLM + ReLU (4th launch for ncu capture).
//    BM=64 x BN=256, BK=16, 256 threads. A stored PLAIN in smem; each warp
//    reads its 8 row-values per k as two broadcast LDS.128 (1 wavefront each)
//    and duplicates in registers (alu-pipe movs) -> LDS drops to 10
//    wavefronts/warp-k, fma pipe becomes the binding resource.
// ---------------------------------------------------------------------------
#define GBM 64
#define GBK 16
__global__ void __launch_bounds__(256, 2)
gemm_ln_kernel(const float* __restrict__ A,
               const float* __restrict__ W,
               const int* __restrict__ batch_ids, int N) {
    __shared__ float As[GBK][68];    // [k][m] plain, row stride 272B (16B-aligned)
    __shared__ float Bs[GBK][260];   // [k][n], padded

    int tid = threadIdx.x;
    int tx = tid & 31, ty = tid >> 5;
    int m0 = blockIdx.x * GBM;

    // A-tile load mapping: thread -> (row am, k-chunk ak = 4 consecutive k)
    int am = tid >> 2;
    int ak = (tid & 3) * 4;
    int arow = m0 + am;
    const float4* Arow = (arow < N) ? (const float4*)(A + (size_t)arow * 256) : 0;

    // B-tile load mapping: 4 float4 per thread
    int bkb = tid >> 6;
    int bn = (tid & 63) * 4;

    unsigned long long acc[8][4];
#pragma unroll
    for (int i = 0; i < 8; i++)
#pragma unroll
        for (int j = 0; j < 4; j++) acc[i][j] = 0ULL;

    // prefetch tile 0
    float4 aR = make_float4(0.f, 0.f, 0.f, 0.f);
    if (Arow) aR = Arow[(tid & 3)];
    float4 bR[4];
#pragma unroll
    for (int i = 0; i < 4; i++)
        bR[i] = *(const float4*)(W + (size_t)(bkb + 4 * i) * 256 + bn);

    for (int kt = 0; kt < 16; kt++) {
        As[ak + 0][am] = aR.x;
        As[ak + 1][am] = aR.y;
        As[ak + 2][am] = aR.z;
        As[ak + 3][am] = aR.w;
#pragma unroll
        for (int i = 0; i < 4; i++)
            *(float4*)&Bs[bkb + 4 * i][bn] = bR[i];
        __syncthreads();

        if (kt < 15) {
            int k0n = (kt + 1) * 16;
            aR = make_float4(0.f, 0.f, 0.f, 0.f);
            if (Arow) aR = Arow[k0n / 4 + (tid & 3)];
#pragma unroll
            for (int i = 0; i < 4; i++)
                bR[i] = *(const float4*)(W + (size_t)(k0n + bkb + 4 * i) * 256 + bn);
        }

#pragma unroll
        for (int k = 0; k < GBK; k++) {
            // broadcast loads: all lanes of warp ty read the same addresses
            float4 aP = *(const float4*)&As[k][ty * 8];
            float4 aQ = *(const float4*)&As[k][ty * 8 + 4];
            ulonglong2 b0 = *(const ulonglong2*)&Bs[k][tx * 4];
            ulonglong2 b1 = *(const ulonglong2*)&Bs[k][128 + tx * 4];

            unsigned long long d0, d1, d2, d3, d4, d5, d6, d7;
            PACK_DUP(d0, aP.x); PACK_DUP(d1, aP.y);
            PACK_DUP(d2, aP.z); PACK_DUP(d3, aP.w);
            PACK_DUP(d4, aQ.x); PACK_DUP(d5, aQ.y);
            PACK_DUP(d6, aQ.z); PACK_DUP(d7, aQ.w);

            FMA_F32X2(acc[0][0], d0, b0.x); FMA_F32X2(acc[0][1], d0, b0.y);
            FMA_F32X2(acc[0][2], d0, b1.x); FMA_F32X2(acc[0][3], d0, b1.y);
            FMA_F32X2(acc[1][0], d1, b0.x); FMA_F32X2(acc[1][1], d1, b0.y);
            FMA_F32X2(acc[1][2], d1, b1.x); FMA_F32X2(acc[1][3], d1, b1.y);
            FMA_F32X2(acc[2][0], d2, b0.x); FMA_F32X2(acc[2][1], d2, b0.y);
            FMA_F32X2(acc[2][2], d2, b1.x); FMA_F32X2(acc[2][3], d2, b1.y);
            FMA_F32X2(acc[3][0], d3, b0.x); FMA_F32X2(acc[3][1], d3, b0.y);
            FMA_F32X2(acc[3][2], d3, b1.x); FMA_F32X2(acc[3][3], d3, b1.y);
            FMA_F32X2(acc[4][0], d4, b0.x); FMA_F32X2(acc[4][1], d4, b0.y);
            FMA_F32X2(acc[4][2], d4, b1.x); FMA_F32X2(acc[4][3], d4, b1.y);
            FMA_F32X2(acc[5][0], d5, b0.x); FMA_F32X2(acc[5][1], d5, b0.y);
            FMA_F32X2(acc[5][2], d5, b1.x); FMA_F32X2(acc[5][3], d5, b1.y);
            FMA_F32X2(acc[6][0], d6, b0.x); FMA_F32X2(acc[6][1], d6, b0.y);
            FMA_F32X2(acc[6][2], d6, b1.x); FMA_F32X2(acc[6][3], d6, b1.y);
            FMA_F32X2(acc[7][0], d7, b0.x); FMA_F32X2(acc[7][1], d7, b0.y);
            FMA_F32X2(acc[7][2], d7, b1.x); FMA_F32X2(acc[7][3], d7, b1.y);
        }
        __syncthreads();
    }

    // ---- epilogue: per-row LayerNorm + FiLM + ReLU, write g_x ----
#pragma unroll
    for (int i = 0; i < 8; i++) {
        float v[8];
        UNPACK2F(v[0], v[1], acc[i][0]);
        UNPACK2F(v[2], v[3], acc[i][1]);
        UNPACK2F(v[4], v[5], acc[i][2]);
        UNPACK2F(v[6], v[7], acc[i][3]);

        float ps = 0.f, pq = 0.f;
#pragma unroll
        for (int j = 0; j < 8; j++) { ps += v[j]; pq = fmaf(v[j], v[j], pq); }
#pragma unroll
        for (int o = 16; o; o >>= 1) {
            ps += __shfl_xor_sync(0xffffffffu, ps, o);
            pq += __shfl_xor_sync(0xffffffffu, pq, o);
        }
        float mu = ps * (1.0f / 256.0f);
        float var = fmaxf(pq * (1.0f / 256.0f) - mu * mu, 0.0f);
        float rs = rsqrtf(var + 1e-5f);

        int row = m0 + ty * 8 + i;
        if (row < N) {
            int b = batch_ids[row];
            const float4* g4 = (const float4*)(g_gamma + b * 256);
            const float4* e4 = (const float4*)(g_beta + b * 256);
            float4 gA = g4[tx], gB = g4[tx + 32];
            float4 eA = e4[tx], eB = e4[tx + 32];

            float4 o0, o1;
            o0.x = fmaxf(fmaf((v[0] - mu) * rs, gA.x, eA.x), 0.f);
            o0.y = fmaxf(fmaf((v[1] - mu) * rs, gA.y, eA.y), 0.f);
            o0.z = fmaxf(fmaf((v[2] - mu) * rs, gA.z, eA.z), 0.f);
            o0.w = fmaxf(fmaf((v[3] - mu) * rs, gA.w, eA.w), 0.f);
            o1.x = fmaxf(fmaf((v[4] - mu) * rs, gB.x, eB.x), 0.f);
            o1.y = fmaxf(fmaf((v[5] - mu) * rs, gB.y, eB.y), 0.f);
            o1.z = fmaxf(fmaf((v[6] - mu) * rs, gB.z, eB.z), 0.f);
            o1.w = fmaxf(fmaf((v[7] - mu) * rs, gB.w, eB.w), 0.f);

            float4* xr = (float4*)(g_x + (size_t)row * 256);
            xr[tx] = o0;
            xr[tx + 32] = o1;
        }
    }
}

// ---------------------------------------------------------------------------
// 6. fill: permute edge payloads into CSR order.
// ---------------------------------------------------------------------------
__global__ void fill_kernel(const int* __restrict__ ni,
                            const int* __restrict__ nj,
                            const float* __restrict__ ew,
                            const float* __restrict__ ep, int E) {
    int e = blockIdx.x * blockDim.x + threadIdx.x;
    if (e < E) {
        int dst = ni[e];
        int p = atomicAdd(&g_cur[dst], 1);
        int pos = g_off[dst] + p;
        g_src[pos] = nj[e];
        g_wgt[pos] = ew[e] * ep[e];
    }
}

// ---------------------------------------------------------------------------
// 7. Pull aggregation: warp per destination node; sequential CSR payloads.
// ---------------------------------------------------------------------------
__global__ void agg_kernel(float* __restrict__ out, int N) {
    int gw = (blockIdx.x * blockDim.x + threadIdx.x) >> 5;
    int lane = threadIdx.x & 31;
    if (gw >= N) return;
    int s = g_off[gw];
    int e = g_off[gw + 1];
    float4 a0 = {0.f, 0.f, 0.f, 0.f};
    float4 a1 = {0.f, 0.f, 0.f, 0.f};
    for (int i = s; i < e; i++) {
        int j = g_src[i];
        float w = g_wgt[i];
        const float4* xr = (const float4*)(g_x + (size_t)j * 256);
        float4 v0 = xr[lane];
        float4 v1 = xr[lane + 32];
        a0.x = fmaf(v0.x, w, a0.x); a0.y = fmaf(v0.y, w, a0.y);
        a0.z = fmaf(v0.z, w, a0.z); a0.w = fmaf(v0.w, w, a0.w);
        a1.x = fmaf(v1.x, w, a1.x); a1.y = fmaf(v1.y, w, a1.y);
        a1.z = fmaf(v1.z, w, a1.z); a1.w = fmaf(v1.w, w, a1.w);
    }
    a0.x = fmaxf(a0.x, 0.f); a0.y = fmaxf(a0.y, 0.f);
    a0.z = fmaxf(a0.z, 0.f); a0.w = fmaxf(a0.w, 0.f);
    a1.x = fmaxf(a1.x, 0.f); a1.y = fmaxf(a1.y, 0.f);
    a1.z = fmaxf(a1.z, 0.f); a1.w = fmaxf(a1.w, 0.f);
    float4* o4 = (float4*)(out + (size_t)gw * 256);
    o4[lane] = a0;
    o4[lane + 32] = a1;
}

// ---------------------------------------------------------------------------
extern "C" void kernel_launch(void* const* d_in, const int* in_sizes, int n_in,
                              void* d_out, int out_size) {
    const float* node_feats = (const float*)d_in[0];
    const float* cond_feats = (const float*)d_in[1];
    const int*   batch_ids  = (const int*)d_in[2];
    const int*   node_j     = (const int*)d_in[3];
    const int*   node_i     = (const int*)d_in[4];
    const float* edge_w     = (const float*)d_in[5];
    const float* edge_p     = (const float*)d_in[6];
    const float* Wc         = (const float*)d_in[7];
    const float* bc         = (const float*)d_in[8];
    const float* Wl         = (const float*)d_in[9];
    float* out = (float*)d_out;

    int N = in_sizes[0] / 256;
    int B = in_sizes[1] / 512;
    int E = in_sizes[3];
    int nblk = (N + 255) / 256;

    // Order chosen so gemm_ln is the 4th launch (ncu capture alignment).
    film_zero_kernel<<<40, 256>>>(cond_feats, Wc, bc, B, N);
    hist_kernel<<<(E + 255) / 256, 256>>>(node_i, E);
    scan_part_kernel<<<nblk, 256>>>(N);
    gemm_ln_kernel<<<(N + GBM - 1) / GBM, 256>>>(node_feats, Wl, batch_ids, N);
    scan_add_kernel<<<nblk, 256>>>(N, E, nblk);
    fill_kernel<<<(E + 255) / 256, 256>>>(node_i, node_j, edge_w, edge_p, E);
    agg_kernel<<<(N * 32 + 255) / 256, 256>>>(out, N);
}

// round 6
// speedup vs baseline: 1.5673x; 1.2163x over previous
#include <cuda_runtime.h>
#include <cuda_bf16.h>
#include <cstdint>

// Problem dims (fixed by dataset): N=20000, E=320000, B=16,
// node_dim=256, cond_dim=512, out_dim=256.
#define NMAX 20000
#define EMAX 320000
#define BMAX 16

// Scratch (allocation-free rule: __device__ globals)
__device__ __align__(16) float g_x[(size_t)NMAX * 256];
__device__ __align__(16) float g_gamma[BMAX * 256];
__device__ __align__(16) float g_beta[BMAX * 256];
__device__ __align__(16) __nv_bfloat16 g_Wh[256 * 256];  // W^T hi, [n][k]
__device__ __align__(16) __nv_bfloat16 g_Wl[256 * 256];  // W^T lo, [n][k]
__device__ int   g_cnt[NMAX];
__device__ int   g_off[NMAX + 1];
__device__ int   g_cur[NMAX];
__device__ int   g_blk[128];
__device__ int   g_src[EMAX];
__device__ float g_wgt[EMAX];

#define SMEM_SWIZZLE_128B(off) ((off) ^ (((off) >> 3) & 0x70))

// warp-level bf16 MMA (baseline PTX, works on compute_103 targets)
__device__ __forceinline__ void mma16816(float* c, const uint32_t* a,
                                         const uint32_t* b) {
    asm volatile(
        "mma.sync.aligned.m16n8k16.row.col.f32.bf16.bf16.f32 "
        "{%0,%1,%2,%3},{%4,%5,%6,%7},{%8,%9},{%0,%1,%2,%3};"
        : "+f"(c[0]), "+f"(c[1]), "+f"(c[2]), "+f"(c[3])
        : "r"(a[0]), "r"(a[1]), "r"(a[2]), "r"(a[3]), "r"(b[0]), "r"(b[1]));
}
__device__ __forceinline__ void ldsm_x4(uint32_t* r, uint32_t addr) {
    asm volatile("ldmatrix.sync.aligned.m8n8.x4.shared.b16 {%0,%1,%2,%3}, [%4];"
                 : "=r"(r[0]), "=r"(r[1]), "=r"(r[2]), "=r"(r[3]) : "r"(addr));
}
__device__ __forceinline__ uint32_t smem_to_u32(const void* p) {
    uint32_t a;
    asm("{ .reg .u64 t; cvta.to.shared.u64 t, %1; cvt.u32.u64 %0, t; }"
        : "=r"(a) : "l"(p));
    return a;
}

// ---------------------------------------------------------------------------
// 0. W prep: split-transpose W[k][n] fp32 -> g_Wh/g_Wl[n][k] bf16.
// ---------------------------------------------------------------------------
__global__ void wprep_kernel(const float* __restrict__ W) {
    __shared__ float t[32][33];
    int bi = blockIdx.x;           // n-tile
    int bj = blockIdx.y;           // k-tile
    int tx = threadIdx.x, ty = threadIdx.y;   // 32 x 8
#pragma unroll
    for (int i = 0; i < 4; i++)
        t[ty + i * 8][tx] = W[(size_t)(bj * 32 + ty + i * 8) * 256 + bi * 32 + tx];
    __syncthreads();
#pragma unroll
    for (int i = 0; i < 4; i++) {
        int n = bi * 32 + ty + i * 8;
        int k = bj * 32 + tx;
        float v = t[tx][ty + i * 8];
        __nv_bfloat16 h = __float2bfloat16_rn(v);
        __nv_bfloat16 l = __float2bfloat16_rn(v - __bfloat162float(h));
        g_Wh[(size_t)n * 256 + k] = h;
        g_Wl[(size_t)n * 256 + k] = l;
    }
}

// ---------------------------------------------------------------------------
// 1. FiLM params + zero CSR counters.
// ---------------------------------------------------------------------------
__global__ void film_zero_kernel(const float* __restrict__ cond,
                                 const float* __restrict__ Wc,
                                 const float* __restrict__ bc, int B, int N) {
    int tid = blockIdx.x * blockDim.x + threadIdx.x;
    for (int i = tid; i < N; i += gridDim.x * blockDim.x) {
        g_cnt[i] = 0; g_cur[i] = 0;
    }
    if (tid >= B * 512) return;
    int b = tid >> 9;
    int o = tid & 511;
    const float* c = cond + b * 512;
    float acc = bc[o];
#pragma unroll 4
    for (int k = 0; k < 512; k++) acc = fmaf(c[k], Wc[k * 512 + o], acc);
    if (o < 256) g_gamma[b * 256 + o] = acc + 1.0f;
    else         g_beta[b * 256 + (o - 256)] = acc;
}

// ---------------------------------------------------------------------------
// 2. hist
// ---------------------------------------------------------------------------
__global__ void hist_kernel(const int* __restrict__ ni, int E) {
    int e = blockIdx.x * blockDim.x + threadIdx.x;
    if (e < E) atomicAdd(&g_cnt[ni[e]], 1);
}

// ---------------------------------------------------------------------------
// 3. Tensor GEMM (mma.sync bf16 3-term split) + LayerNorm + FiLM + ReLU.
//    CTA: 64 rows x 256 cols, 256 threads = 8 warps (2 m-warps x 4 n-warps),
//    warp tile 32x64. K staged in 4 chunks of 64.
//    SMEM: Ah 8K | Al 8K | Wh 32K | Wl 32K | stats 512B = 80.5 KB.
// ---------------------------------------------------------------------------
#define SM_AH 0
#define SM_AL 8192
#define SM_WH 16384
#define SM_WL 49152
#define SM_ST 81920
#define SM_TOTAL (81920 + 512)

__global__ void __launch_bounds__(256, 2)
gemm_ln_kernel(const float* __restrict__ A,
               const int* __restrict__ batch_ids, int N) {
    extern __shared__ char sm[];
    uint32_t smb = smem_to_u32(sm);
    float* s_sum = (float*)(sm + SM_ST);        // [64]
    float* s_sq  = (float*)(sm + SM_ST + 256);  // [64]

    int tid = threadIdx.x;
    int wid = tid >> 5, lane = tid & 31;
    int mw = wid >> 2;           // 0..1  m-warp
    int nw = wid & 3;            // 0..3  n-warp
    int m0 = blockIdx.x * 64;

    if (tid < 128) ((float*)(sm + SM_ST))[tid] = 0.0f;

    // ldmatrix per-lane addressing
    int g = lane >> 3;           // matrix index 0..3
    int lr = lane & 7;
    uint32_t axor = (uint32_t)(lr << 4);
    // A frags: matrices {rows+0,k0},{rows+8,k0},{rows+0,k8},{rows+8,k8}
    uint32_t a_rowb0 = (uint32_t)((mw * 32 + 0  + (g & 1) * 8 + lr) * 128);
    uint32_t a_rowb1 = (uint32_t)((mw * 32 + 16 + (g & 1) * 8 + lr) * 128);
    uint32_t a_k16 = (uint32_t)((g >> 1) * 16);
    // B frags: matrices {nt0,k0},{nt0,k8},{nt1,k0},{nt1,k8}
    uint32_t b_rowb = (uint32_t)((nw * 64 + ((g >> 1) & 1) * 8 + lr) * 128);
    uint32_t b_k16 = (uint32_t)((g & 1) * 16);

    float c[2][8][4];
#pragma unroll
    for (int i = 0; i < 2; i++)
#pragma unroll
        for (int j = 0; j < 8; j++)
#pragma unroll
            for (int q = 0; q < 4; q++) c[i][j][q] = 0.0f;

    for (int kt = 0; kt < 4; kt++) {
        // ---- stage A chunk [64 rows x 64 k] fp32 -> bf16 hi/lo, swizzled
#pragma unroll
        for (int it = 0; it < 2; it++) {
            int item = it * 256 + tid;
            int r = item >> 3, kk = (item & 7) * 8;
            uint4 hv = make_uint4(0, 0, 0, 0), lv = make_uint4(0, 0, 0, 0);
            int row = m0 + r;
            if (row < N) {
                const float* p = A + (size_t)row * 256 + kt * 64 + kk;
                float4 f0 = *(const float4*)p;
                float4 f1 = *(const float4*)(p + 4);
                float f[8] = {f0.x, f0.y, f0.z, f0.w, f1.x, f1.y, f1.z, f1.w};
                uint32_t h[4], l[4];
#pragma unroll
                for (int q = 0; q < 4; q++) {
                    __nv_bfloat16 h0 = __float2bfloat16_rn(f[2 * q]);
                    __nv_bfloat16 h1 = __float2bfloat16_rn(f[2 * q + 1]);
                    __nv_bfloat16 l0 = __float2bfloat16_rn(f[2 * q] - __bfloat162float(h0));
                    __nv_bfloat16 l1 = __float2bfloat16_rn(f[2 * q + 1] - __bfloat162float(h1));
                    h[q] = ((uint32_t)__bfloat16_as_ushort(h1) << 16) | __bfloat16_as_ushort(h0);
                    l[q] = ((uint32_t)__bfloat16_as_ushort(l1) << 16) | __bfloat16_as_ushort(l0);
                }
                hv = make_uint4(h[0], h[1], h[2], h[3]);
                lv = make_uint4(l[0], l[1], l[2], l[3]);
            }
            uint32_t sw = SMEM_SWIZZLE_128B((uint32_t)(r * 128 + kk * 2));
            *(uint4*)(sm + SM_AH + sw) = hv;
            *(uint4*)(sm + SM_AL + sw) = lv;
        }
        // ---- stage W chunk [256 n x 64 k] bf16 hi/lo, swizzled
#pragma unroll
        for (int it = 0; it < 8; it++) {
            int item = it * 256 + tid;
            int n = item >> 3, kk = (item & 7) * 8;
            uint32_t sw = SMEM_SWIZZLE_128B((uint32_t)(n * 128 + kk * 2));
            size_t go = (size_t)n * 512 + kt * 128 + kk * 2;   // bytes
            *(uint4*)(sm + SM_WH + sw) = *(const uint4*)((const char*)g_Wh + go);
            *(uint4*)(sm + SM_WL + sw) = *(const uint4*)((const char*)g_Wl + go);
        }
        __syncthreads();

#pragma unroll
        for (int ks = 0; ks < 4; ks++) {
            uint32_t ko = (uint32_t)(ks * 32);
            uint32_t ah0[4], ah1[4], al0[4], al1[4];
            ldsm_x4(ah0, smb + SM_AH + a_rowb0 + ((ko + a_k16) ^ axor));
            ldsm_x4(ah1, smb + SM_AH + a_rowb1 + ((ko + a_k16) ^ axor));
            ldsm_x4(al0, smb + SM_AL + a_rowb0 + ((ko + a_k16) ^ axor));
            ldsm_x4(al1, smb + SM_AL + a_rowb1 + ((ko + a_k16) ^ axor));
#pragma unroll
            for (int np = 0; np < 4; np++) {
                uint32_t bh[4], bl[4];
                uint32_t baddr = b_rowb + (uint32_t)(np * 2048) + ((ko + b_k16) ^ axor);
                ldsm_x4(bh, smb + SM_WH + baddr);
                ldsm_x4(bl, smb + SM_WL + baddr);
                // n-tile 2*np
                mma16816(c[0][2 * np], ah0, bh);
                mma16816(c[0][2 * np], al0, bh);
                mma16816(c[0][2 * np], ah0, bl);
                mma16816(c[1][2 * np], ah1, bh);
                mma16816(c[1][2 * np], al1, bh);
                mma16816(c[1][2 * np], ah1, bl);
                // n-tile 2*np+1
                mma16816(c[0][2 * np + 1], ah0, bh + 2);
                mma16816(c[0][2 * np + 1], al0, bh + 2);
                mma16816(c[0][2 * np + 1], ah0, bl + 2);
                mma16816(c[1][2 * np + 1], ah1, bh + 2);
                mma16816(c[1][2 * np + 1], al1, bh + 2);
                mma16816(c[1][2 * np + 1], ah1, bl + 2);
            }
        }
        __syncthreads();
    }

    // ---- LN stats: quad-shuffle partials, smem atomics across n-warps ----
#pragma unroll
    for (int tm = 0; tm < 2; tm++) {
#pragma unroll
        for (int h = 0; h < 2; h++) {
            int rl = mw * 32 + tm * 16 + h * 8 + (lane >> 2);
            float ps = 0.f, pq = 0.f;
#pragma unroll
            for (int nt = 0; nt < 8; nt++) {
                float v0 = c[tm][nt][2 * h], v1 = c[tm][nt][2 * h + 1];
                ps += v0 + v1;
                pq = fmaf(v0, v0, fmaf(v1, v1, pq));
            }
            ps += __shfl_xor_sync(0xffffffffu, ps, 1);
            pq += __shfl_xor_sync(0xffffffffu, pq, 1);
            ps += __shfl_xor_sync(0xffffffffu, ps, 2);
            pq += __shfl_xor_sync(0xffffffffu, pq, 2);
            if ((lane & 3) == 0) {
                atomicAdd(&s_sum[rl], ps);
                atomicAdd(&s_sq[rl], pq);
            }
        }
    }
    __syncthreads();

    // ---- normalize + FiLM + ReLU from fragments -> g_x ----
#pragma unroll
    for (int tm = 0; tm < 2; tm++) {
#pragma unroll
        for (int h = 0; h < 2; h++) {
            int rl = mw * 32 + tm * 16 + h * 8 + (lane >> 2);
            int row = m0 + rl;
            if (row >= N) continue;
            float mu = s_sum[rl] * (1.0f / 256.0f);
            float var = fmaxf(s_sq[rl] * (1.0f / 256.0f) - mu * mu, 0.0f);
            float rs = rsqrtf(var + 1e-5f);
            int b = batch_ids[row];
            const float* gg = g_gamma + b * 256;
            const float* bb = g_beta + b * 256;
            float* xo = g_x + (size_t)row * 256;
#pragma unroll
            for (int nt = 0; nt < 8; nt++) {
                int col = nw * 64 + nt * 8 + (lane & 3) * 2;
                float2 gv = *(const float2*)(gg + col);
                float2 ev = *(const float2*)(bb + col);
                float2 o;
                o.x = fmaxf(fmaf((c[tm][nt][2 * h] - mu) * rs, gv.x, ev.x), 0.f);
                o.y = fmaxf(fmaf((c[tm][nt][2 * h + 1] - mu) * rs, gv.y, ev.y), 0.f);
                *(float2*)(xo + col) = o;
            }
        }
    }
}

// ---------------------------------------------------------------------------
// scan_part / scan_add / fill / agg (unchanged)
// ---------------------------------------------------------------------------
__global__ void scan_part_kernel(int N) {
    __shared__ int wsum[8];
    int idx = blockIdx.x * 256 + threadIdx.x;
    int lane = threadIdx.x & 31;
    int wid = threadIdx.x >> 5;
    int v = (idx < N) ? g_cnt[idx] : 0;
    int s = v;
#pragma unroll
    for (int o = 1; o < 32; o <<= 1) {
        int t = __shfl_up_sync(0xffffffffu, s, o);
        if (lane >= o) s += t;
    }
    if (lane == 31) wsum[wid] = s;
    __syncthreads();
    if (wid == 0) {
        int ws = (lane < 8) ? wsum[lane] : 0;
#pragma unroll
        for (int o = 1; o < 8; o <<= 1) {
            int t = __shfl_up_sync(0xffffffffu, ws, o);
            if (lane >= o) ws += t;
        }
        if (lane < 8) wsum[lane] = ws;
    }
    __syncthreads();
    int excl = s - v + (wid ? wsum[wid - 1] : 0);
    if (idx < N) g_off[idx] = excl;
    if (threadIdx.x == 255) g_blk[blockIdx.x] = excl + v;
}

__global__ void scan_add_kernel(int N, int E, int nblk) {
    __shared__ int prefix;
    int bid = blockIdx.x;
    if (threadIdx.x < 32) {
        int acc = 0;
        for (int t = threadIdx.x; t < bid; t += 32) acc += g_blk[t];
#pragma unroll
        for (int o = 16; o; o >>= 1) acc += __shfl_xor_sync(0xffffffffu, acc, o);
        if (threadIdx.x == 0) prefix = acc;
    }
    __syncthreads();
    int idx = bid * 256 + threadIdx.x;
    if (idx < N && bid > 0) g_off[idx] += prefix;
    if (idx == 0) g_off[N] = E;
}

__global__ void fill_kernel(const int* __restrict__ ni,
                            const int* __restrict__ nj,
                            const float* __restrict__ ew,
                            const float* __restrict__ ep, int E) {
    int e = blockIdx.x * blockDim.x + threadIdx.x;
    if (e < E) {
        int dst = ni[e];
        int p = atomicAdd(&g_cur[dst], 1);
        int pos = g_off[dst] + p;
        g_src[pos] = nj[e];
        g_wgt[pos] = ew[e] * ep[e];
    }
}

__global__ void agg_kernel(float* __restrict__ out, int N) {
    int gw = (blockIdx.x * blockDim.x + threadIdx.x) >> 5;
    int lane = threadIdx.x & 31;
    if (gw >= N) return;
    int s = g_off[gw];
    int e = g_off[gw + 1];
    float4 a0 = {0.f, 0.f, 0.f, 0.f};
    float4 a1 = {0.f, 0.f, 0.f, 0.f};
    for (int i = s; i < e; i++) {
        int j = g_src[i];
        float w = g_wgt[i];
        const float4* xr = (const float4*)(g_x + (size_t)j * 256);
        float4 v0 = xr[lane];
        float4 v1 = xr[lane + 32];
        a0.x = fmaf(v0.x, w, a0.x); a0.y = fmaf(v0.y, w, a0.y);
        a0.z = fmaf(v0.z, w, a0.z); a0.w = fmaf(v0.w, w, a0.w);
        a1.x = fmaf(v1.x, w, a1.x); a1.y = fmaf(v1.y, w, a1.y);
        a1.z = fmaf(v1.z, w, a1.z); a1.w = fmaf(v1.w, w, a1.w);
    }
    a0.x = fmaxf(a0.x, 0.f); a0.y = fmaxf(a0.y, 0.f);
    a0.z = fmaxf(a0.z, 0.f); a0.w = fmaxf(a0.w, 0.f);
    a1.x = fmaxf(a1.x, 0.f); a1.y = fmaxf(a1.y, 0.f);
    a1.z = fmaxf(a1.z, 0.f); a1.w = fmaxf(a1.w, 0.f);
    float4* o4 = (float4*)(out + (size_t)gw * 256);
    o4[lane] = a0;
    o4[lane + 32] = a1;
}

// ---------------------------------------------------------------------------
extern "C" void kernel_launch(void* const* d_in, const int* in_sizes, int n_in,
                              void* d_out, int out_size) {
    const float* node_feats = (const float*)d_in[0];
    const float* cond_feats = (const float*)d_in[1];
    const int*   batch_ids  = (const int*)d_in[2];
    const int*   node_j     = (const int*)d_in[3];
    const int*   node_i     = (const int*)d_in[4];
    const float* edge_w     = (const float*)d_in[5];
    const float* edge_p     = (const float*)d_in[6];
    const float* Wc         = (const float*)d_in[7];
    const float* bc         = (const float*)d_in[8];
    const float* Wl         = (const float*)d_in[9];
    float* out = (float*)d_out;

    int N = in_sizes[0] / 256;
    int B = in_sizes[1] / 512;
    int E = in_sizes[3];
    int nblk = (N + 255) / 256;

    static int smem_set = 0;
    if (!smem_set) {
        cudaFuncSetAttribute(gemm_ln_kernel,
                             cudaFuncAttributeMaxDynamicSharedMemorySize, SM_TOTAL);
        smem_set = 1;
    }

    // Order: gemm_ln is the 4th launch (ncu capture alignment).
    wprep_kernel<<<dim3(8, 8), dim3(32, 8)>>>(Wl);
    film_zero_kernel<<<40, 256>>>(cond_feats, Wc, bc, B, N);
    hist_kernel<<<(E + 255) / 256, 256>>>(node_i, E);
    gemm_ln_kernel<<<(N + 63) / 64, 256, SM_TOTAL>>>(node_feats, batch_ids, N);
    scan_part_kernel<<<nblk, 256>>>(N);
    scan_add_kernel<<<nblk, 256>>>(N, E, nblk);
    fill_kernel<<<(E + 255) / 256, 256>>>(node_i, node_j, edge_w, edge_p, E);
    agg_kernel<<<(N * 32 + 255) / 256, 256>>>(out, N);
}